// round 2
// baseline (speedup 1.0000x reference)
#include <cuda_runtime.h>

#define B_ 256
#define T_ 512
#define C_ 256
#define L_ 64
#define S_ 129      // 2L+1 extended states
#define PS 132      // padded pg row stride (16B-aligned float4 rows)

// Scratch (allocation-free rule: __device__ globals). ~69 MB.
__device__ float g_pg[(size_t)B_ * T_ * PS + 64];
__device__ float g_loss[B_];

// ---------------------------------------------------------------------------
// Kernel 1: warp-per-(b,t)-row softmax + gather into extended-label order.
// No block barriers: each warp is fully independent.
//   pg[b,t,s] = exp(logits[b,t,ext[s]]) / sum_c exp(logits[b,t,c])
// Lane writes s = 4*lane..4*lane+3 as one float4; lane 0 also writes s=128.
// ---------------------------------------------------------------------------
__global__ void __launch_bounds__(256) probs_kernel(
    const float* __restrict__ logits, const int* __restrict__ targets) {
  int warp = threadIdx.x >> 5, lane = threadIdx.x & 31;
  size_t row = (size_t)blockIdx.x * 8 + warp;   // row = b*T + t
  int b = (int)(row >> 9);                      // T_ = 512

  __shared__ float sh[8][C_];

  const float4* lrow = (const float4*)(logits + row * C_);
  float4 v0 = lrow[lane];        // c = 4*lane
  float4 v1 = lrow[lane + 32];   // c = 128 + 4*lane
  float4 e0, e1;
  e0.x = __expf(v0.x); e0.y = __expf(v0.y); e0.z = __expf(v0.z); e0.w = __expf(v0.w);
  e1.x = __expf(v1.x); e1.y = __expf(v1.y); e1.z = __expf(v1.z); e1.w = __expf(v1.w);

  float s = ((e0.x + e0.y) + (e0.z + e0.w)) + ((e1.x + e1.y) + (e1.z + e1.w));
  #pragma unroll
  for (int o = 16; o; o >>= 1) s += __shfl_xor_sync(0xffffffffu, s, o);
  float inv = __frcp_rn(s);

  ((float4*)sh[warp])[lane]      = e0;
  ((float4*)sh[warp])[lane + 32] = e1;
  __syncwarp();

  // s = 4l+0 (blank), 4l+1 (label 2l), 4l+2 (blank), 4l+3 (label 2l+1)
  int2 tv = ((const int2*)(targets + b * L_))[lane];
  float eb = sh[warp][0] * inv;
  float4 o;
  o.x = eb;
  o.y = sh[warp][tv.x] * inv;
  o.z = eb;
  o.w = sh[warp][tv.y] * inv;

  float* orow = g_pg + row * PS;
  ((float4*)orow)[lane] = o;
  if (lane == 0) orow[128] = eb;   // s = 128 (blank)
}

// ---------------------------------------------------------------------------
// Kernel 2: linear-domain CTC forward, one warp per batch row.
// Lane l owns 5 consecutive states s = 5l..5l+4 in registers. Per step:
// two shfl_up for the cross-lane neighbors, pure FMA for the rest. No smem,
// no syncwarp in the hot loop. Power-of-2 renorm every 4 steps via REDUX
// on the float bit pattern (all alphas >= 0). 8-deep prefetch of pg rows.
// ---------------------------------------------------------------------------
__global__ void __launch_bounds__(32) alpha_kernel(
    const int* __restrict__ targets,
    const int* __restrict__ input_lengths,
    const int* __restrict__ target_lengths) {
  int b = blockIdx.x;
  int lane = threadIdx.x;
  int len = input_lengths[b];
  int tl = target_lengths[b];
  int Sb = 2 * tl + 1;

  const float* __restrict__ pgb = g_pg + (size_t)b * T_ * PS;
  const int* __restrict__ tg = targets + b * L_;

  int s0 = 5 * lane;
  float skipm[5];
  bool pm[5];
  #pragma unroll
  for (int j = 0; j < 5; j++) {
    int s = s0 + j;
    pm[j] = (s < Sb);
    float sm = 0.f;
    if ((s & 1) && s >= 3 && s < S_) {       // odd non-blank, s>=3
      int q = s >> 1;
      sm = (tg[q] != tg[q - 1]) ? 1.f : 0.f;
    }
    skipm[j] = sm;
  }

  // t = 0: alpha[0] = p(blank), alpha[1] = p(label0)
  float a[5];
  #pragma unroll
  for (int j = 0; j < 5; j++) {
    int s = s0 + j;
    a[j] = (s < 2) ? pgb[s] : 0.f;
  }

  // 8-deep prefetch ring: rows t..t+7 live in pbuf[2][4][5]
  float pbuf[2][4][5];
  #pragma unroll
  for (int ph = 0; ph < 2; ph++)
    #pragma unroll
    for (int u = 0; u < 4; u++) {
      int r = 1 + ph * 4 + u;
      const float* prow = pgb + (size_t)r * PS;
      #pragma unroll
      for (int j = 0; j < 5; j++)
        pbuf[ph][u][j] = pm[j] ? prow[s0 + j] : 0.f;
    }

  int e_total = 0;
  int nsteps = len - 1;            // len in [412, 512]
  int nchunk = nsteps >> 2;
  int t = 1;

  for (int ch = 0; ch < nchunk; ch++) {
    int phase = ch & 1;
    #pragma unroll
    for (int u = 0; u < 4; u++) {
      float pv[5];
      #pragma unroll
      for (int j = 0; j < 5; j++) pv[j] = pbuf[phase][u][j];

      // prefetch row t+u+8 into the slot just freed
      int tp = t + u + 8;
      if (tp < T_) {
        const float* prow = pgb + (size_t)tp * PS;
        #pragma unroll
        for (int j = 0; j < 5; j++)
          pbuf[phase][u][j] = pm[j] ? prow[s0 + j] : 0.f;
      }

      float up1 = __shfl_up_sync(0xffffffffu, a[4], 1);  // alpha[s0-1]
      float up2 = __shfl_up_sync(0xffffffffu, a[3], 1);  // alpha[s0-2]
      if (lane == 0) { up1 = 0.f; up2 = 0.f; }

      float n0 = fmaf(skipm[0], up2,  a[0] + up1) * pv[0];
      float n1 = fmaf(skipm[1], up1,  a[1] + a[0]) * pv[1];
      float n2 = fmaf(skipm[2], a[0], a[2] + a[1]) * pv[2];
      float n3 = fmaf(skipm[3], a[1], a[3] + a[2]) * pv[3];
      float n4 = fmaf(skipm[4], a[2], a[4] + a[3]) * pv[4];
      a[0] = n0; a[1] = n1; a[2] = n2; a[3] = n3; a[4] = n4;

      if (u == 3) {   // power-of-2 renorm every 4 steps
        float lm = fmaxf(fmaxf(a[0], a[1]), fmaxf(fmaxf(a[2], a[3]), a[4]));
        unsigned mb = __reduce_max_sync(0xffffffffu, __float_as_uint(lm));
        int e = (int)(mb >> 23) - 127;
        if (mb != 0u && e != 0) {
          float f = __int_as_float((127 - e) << 23);   // 2^(-e)
          #pragma unroll
          for (int j = 0; j < 5; j++) a[j] *= f;
          e_total += e;
        }
      }
    }
    t += 4;
  }

  // remainder (<= 3 steps), direct loads
  for (; t < len; t++) {
    const float* prow = pgb + (size_t)t * PS;
    float pv[5];
    #pragma unroll
    for (int j = 0; j < 5; j++) pv[j] = pm[j] ? prow[s0 + j] : 0.f;
    float up1 = __shfl_up_sync(0xffffffffu, a[4], 1);
    float up2 = __shfl_up_sync(0xffffffffu, a[3], 1);
    if (lane == 0) { up1 = 0.f; up2 = 0.f; }
    float n0 = fmaf(skipm[0], up2,  a[0] + up1) * pv[0];
    float n1 = fmaf(skipm[1], up1,  a[1] + a[0]) * pv[1];
    float n2 = fmaf(skipm[2], a[0], a[2] + a[1]) * pv[2];
    float n3 = fmaf(skipm[3], a[1], a[3] + a[2]) * pv[3];
    float n4 = fmaf(skipm[4], a[2], a[4] + a[3]) * pv[4];
    a[0] = n0; a[1] = n1; a[2] = n2; a[3] = n3; a[4] = n4;
  }

  // gather alpha[2tl], alpha[2tl-1] via shared scratch
  __shared__ float shf[176];
  #pragma unroll
  for (int j = 0; j < 5; j++) shf[s0 + j] = a[j];   // max index 159
  __syncwarp();
  if (lane == 0) {
    float ssum = shf[2 * tl] + shf[2 * tl - 1];
    float loss = -(logf(ssum) + (float)e_total * 0.69314718055994530942f);
    if (!isfinite(loss) || loss > 1e20f) loss = 0.f;   // zero_infinity
    g_loss[b] = loss / (float)tl;
  }
}

// ---------------------------------------------------------------------------
// Kernel 3: deterministic mean over batch.
// ---------------------------------------------------------------------------
__global__ void __launch_bounds__(256) finalize_kernel(float* __restrict__ out) {
  int i = threadIdx.x;
  float v = g_loss[i];
  #pragma unroll
  for (int o = 16; o; o >>= 1) v += __shfl_xor_sync(0xffffffffu, v, o);
  __shared__ float ws[8];
  if ((i & 31) == 0) ws[i >> 5] = v;
  __syncthreads();
  if (i == 0) {
    float s = 0.f;
    #pragma unroll
    for (int w = 0; w < 8; w++) s += ws[w];
    out[0] = s * (1.0f / (float)B_);
  }
}

extern "C" void kernel_launch(void* const* d_in, const int* in_sizes, int n_in,
                              void* d_out, int out_size) {
  const float* logits         = (const float*)d_in[0];
  const int*   targets        = (const int*)d_in[1];
  const int*   input_lengths  = (const int*)d_in[2];
  const int*   target_lengths = (const int*)d_in[3];
  (void)in_sizes; (void)n_in; (void)out_size;

  probs_kernel<<<(B_ * T_) / 8, 256>>>(logits, targets);
  alpha_kernel<<<B_, 32>>>(targets, input_lengths, target_lengths);
  finalize_kernel<<<1, 256>>>((float*)d_out);
}

// round 5
// speedup vs baseline: 3.0886x; 3.0886x over previous
#include <cuda_runtime.h>

#define B_ 256
#define T_ 512
#define C_ 256
#define L_ 64
#define S_ 129      // 2L+1 extended states
#define PS 132      // padded pg row stride (16B-aligned float4 rows)

// Scratch (allocation-free rule: __device__ globals). ~69 MB.
__device__ float g_pg[(size_t)B_ * T_ * PS + 64];
__device__ float g_loss[B_];

// ---------------------------------------------------------------------------
// Kernel 1: warp-per-(b,t)-row softmax + gather into extended-label order.
// At the memory roofline (203 MB total traffic, ~5.3 TB/s) — unchanged.
// ---------------------------------------------------------------------------
__global__ void __launch_bounds__(256) probs_kernel(
    const float* __restrict__ logits, const int* __restrict__ targets) {
  int warp = threadIdx.x >> 5, lane = threadIdx.x & 31;
  size_t row = (size_t)blockIdx.x * 8 + warp;   // row = b*T + t
  int b = (int)(row >> 9);                      // T_ = 512

  __shared__ float sh[8][C_];

  const float4* lrow = (const float4*)(logits + row * C_);
  float4 v0 = lrow[lane];        // c = 4*lane
  float4 v1 = lrow[lane + 32];   // c = 128 + 4*lane
  float4 e0, e1;
  e0.x = __expf(v0.x); e0.y = __expf(v0.y); e0.z = __expf(v0.z); e0.w = __expf(v0.w);
  e1.x = __expf(v1.x); e1.y = __expf(v1.y); e1.z = __expf(v1.z); e1.w = __expf(v1.w);

  float s = ((e0.x + e0.y) + (e0.z + e0.w)) + ((e1.x + e1.y) + (e1.z + e1.w));
  #pragma unroll
  for (int o = 16; o; o >>= 1) s += __shfl_xor_sync(0xffffffffu, s, o);
  float inv = __frcp_rn(s);

  ((float4*)sh[warp])[lane]      = e0;
  ((float4*)sh[warp])[lane + 32] = e1;
  __syncwarp();

  // s = 4l+0 (blank), 4l+1 (label 2l), 4l+2 (blank), 4l+3 (label 2l+1)
  int2 tv = ((const int2*)(targets + b * L_))[lane];
  float eb = sh[warp][0] * inv;
  float4 o;
  o.x = eb;
  o.y = sh[warp][tv.x] * inv;
  o.z = eb;
  o.w = sh[warp][tv.y] * inv;

  float* orow = g_pg + row * PS;
  ((float4*)orow)[lane] = o;
  if (lane == 0) orow[128] = eb;   // s = 128 (blank)
}

// ---------------------------------------------------------------------------
// Kernel 2: linear-domain CTC forward, one warp per batch row.
// Lane l owns 5 consecutive states s = 5l..5l+4 in registers. Two shfl_up per
// step for cross-lane neighbors; rest is register FMA. Renorm by 2^-e every
// 4 steps via REDUX on the float bits.
// Prefetch buffers pA/pB are separate statically-indexed register arrays,
// refilled in fully unrolled phases (runtime-indexed ring in R2 spilled to
// local memory and cost 2.7x).
// ---------------------------------------------------------------------------
__global__ void __launch_bounds__(32) alpha_kernel(
    const int* __restrict__ targets,
    const int* __restrict__ input_lengths,
    const int* __restrict__ target_lengths) {
  int b = blockIdx.x;
  int lane = threadIdx.x;
  int len = input_lengths[b];
  int tl = target_lengths[b];
  int Sb = 2 * tl + 1;

  const float* __restrict__ pgb = g_pg + (size_t)b * T_ * PS;
  const int* __restrict__ tg = targets + b * L_;

  int s0 = 5 * lane;
  float skipm[5];
  bool pm[5];
  #pragma unroll
  for (int j = 0; j < 5; j++) {
    int s = s0 + j;
    pm[j] = (s < Sb);
    float sm = 0.f;
    if ((s & 1) && s >= 3 && s < S_) {       // odd non-blank, s>=3
      int q = s >> 1;
      sm = (tg[q] != tg[q - 1]) ? 1.f : 0.f;
    }
    skipm[j] = sm;
  }

  // t = 0: alpha[0] = p(blank), alpha[1] = p(label0)
  float a[5];
  #pragma unroll
  for (int j = 0; j < 5; j++) {
    int s = s0 + j;
    a[j] = (s < 2) ? pgb[s] : 0.f;
  }

  // 8-deep prefetch: pA holds rows t..t+3, pB rows t+4..t+7 (all static idx)
  float pA[4][5], pB[4][5];
  #pragma unroll
  for (int u = 0; u < 4; u++) {
    const float* prA = pgb + (size_t)(1 + u) * PS;
    const float* prB = pgb + (size_t)(5 + u) * PS;
    #pragma unroll
    for (int j = 0; j < 5; j++) {
      pA[u][j] = pm[j] ? __ldg(prA + s0 + j) : 0.f;
      pB[u][j] = pm[j] ? __ldg(prB + s0 + j) : 0.f;
    }
  }

  int e_total = 0;
  int nsteps = len - 1;            // len in [412, 512]
  int nblk8 = nsteps >> 3;
  int t = 1;

#define CTC_STEP(PV)                                                     \
  do {                                                                   \
    float up1 = __shfl_up_sync(0xffffffffu, a[4], 1);                    \
    float up2 = __shfl_up_sync(0xffffffffu, a[3], 1);                    \
    if (lane == 0) { up1 = 0.f; up2 = 0.f; }                             \
    float n0 = fmaf(skipm[0], up2,  a[0] + up1) * (PV)[0];               \
    float n1 = fmaf(skipm[1], up1,  a[1] + a[0]) * (PV)[1];              \
    float n2 = fmaf(skipm[2], a[0], a[2] + a[1]) * (PV)[2];              \
    float n3 = fmaf(skipm[3], a[1], a[3] + a[2]) * (PV)[3];              \
    float n4 = fmaf(skipm[4], a[2], a[4] + a[3]) * (PV)[4];              \
    a[0] = n0; a[1] = n1; a[2] = n2; a[3] = n3; a[4] = n4;               \
  } while (0)

#define CTC_RENORM()                                                     \
  do {                                                                   \
    float lm = fmaxf(fmaxf(a[0], a[1]), fmaxf(fmaxf(a[2], a[3]), a[4])); \
    unsigned mb = __reduce_max_sync(0xffffffffu, __float_as_uint(lm));   \
    int e = (int)(mb >> 23) - 127;                                       \
    if (mb != 0u && e != 0) {                                            \
      float f = __int_as_float((127 - e) << 23);  /* 2^(-e) */           \
      a[0] *= f; a[1] *= f; a[2] *= f; a[3] *= f; a[4] *= f;             \
      e_total += e;                                                      \
    }                                                                    \
  } while (0)

  for (int blk = 0; blk < nblk8; blk++) {
    // phase A: consume rows t..t+3, refill pA with rows t+8..t+11
    #pragma unroll
    for (int u = 0; u < 4; u++) {
      float pv[5];
      #pragma unroll
      for (int j = 0; j < 5; j++) pv[j] = pA[u][j];
      int tp = t + u + 8;
      if (tp < T_) {
        const float* prow = pgb + (size_t)tp * PS;
        #pragma unroll
        for (int j = 0; j < 5; j++) pA[u][j] = pm[j] ? __ldg(prow + s0 + j) : 0.f;
      }
      CTC_STEP(pv);
      if (u == 3) CTC_RENORM();
    }
    // phase B: consume rows t+4..t+7, refill pB with rows t+12..t+15
    #pragma unroll
    for (int u = 0; u < 4; u++) {
      float pv[5];
      #pragma unroll
      for (int j = 0; j < 5; j++) pv[j] = pB[u][j];
      int tp = t + u + 12;
      if (tp < T_) {
        const float* prow = pgb + (size_t)tp * PS;
        #pragma unroll
        for (int j = 0; j < 5; j++) pB[u][j] = pm[j] ? __ldg(prow + s0 + j) : 0.f;
      }
      CTC_STEP(pv);
      if (u == 3) CTC_RENORM();
    }
    t += 8;
  }

  // remainder (<= 7 steps): rows t..t+6 are already prefetched in pA/pB
  {
    int rem = len - t;           // 0..7
    #pragma unroll
    for (int u = 0; u < 4; u++) {
      if (u < rem) { CTC_STEP(pA[u]); }
    }
    #pragma unroll
    for (int u = 0; u < 4; u++) {
      if (u + 4 < rem) { CTC_STEP(pB[u]); }
    }
  }

  // gather alpha[2tl], alpha[2tl-1] via shared scratch
  __shared__ float shf[176];
  #pragma unroll
  for (int j = 0; j < 5; j++) shf[s0 + j] = a[j];   // max index 159
  __syncwarp();
  if (lane == 0) {
    float ssum = shf[2 * tl] + shf[2 * tl - 1];
    float loss = -(logf(ssum) + (float)e_total * 0.69314718055994530942f);
    if (!isfinite(loss) || loss > 1e20f) loss = 0.f;   // zero_infinity
    g_loss[b] = loss / (float)tl;
  }
#undef CTC_STEP
#undef CTC_RENORM
}

// ---------------------------------------------------------------------------
// Kernel 3: deterministic mean over batch.
// ---------------------------------------------------------------------------
__global__ void __launch_bounds__(256) finalize_kernel(float* __restrict__ out) {
  int i = threadIdx.x;
  float v = g_loss[i];
  #pragma unroll
  for (int o = 16; o; o >>= 1) v += __shfl_xor_sync(0xffffffffu, v, o);
  __shared__ float ws[8];
  if ((i & 31) == 0) ws[i >> 5] = v;
  __syncthreads();
  if (i == 0) {
    float s = 0.f;
    #pragma unroll
    for (int w = 0; w < 8; w++) s += ws[w];
    out[0] = s * (1.0f / (float)B_);
  }
}

extern "C" void kernel_launch(void* const* d_in, const int* in_sizes, int n_in,
                              void* d_out, int out_size) {
  const float* logits         = (const float*)d_in[0];
  const int*   targets        = (const int*)d_in[1];
  const int*   input_lengths  = (const int*)d_in[2];
  const int*   target_lengths = (const int*)d_in[3];
  (void)in_sizes; (void)n_in; (void)out_size;

  probs_kernel<<<(B_ * T_) / 8, 256>>>(logits, targets);
  alpha_kernel<<<B_, 32>>>(targets, input_lengths, target_lengths);
  finalize_kernel<<<1, 256>>>((float*)d_out);
}